// round 6
// baseline (speedup 1.0000x reference)
#include <cuda_runtime.h>
#include <math.h>

// Problem constants
#define BB   32
#define DD   1024
#define NI_  1024
#define PP   1000
#define RR   3
#define SCALE 0.03125f   // 1/sqrt(1024)
#define SPLITK 32
#define KC   16
#define TN   64          // N tile
#define NTHREADS 256

// ---------------------------------------------------------------------------
// Scratch (device globals; no allocation allowed)
// ---------------------------------------------------------------------------
__device__ float g_qall_part  [SPLITK * RR * BB * DD];
__device__ float g_qall       [RR * BB * DD];
__device__ float g_scores_part[SPLITK * RR * BB * PP];
__device__ float g_weights    [RR * BB * PP];
__device__ float g_vagg_part  [SPLITK * RR * BB * DD];
__device__ float g_vagg       [BB * DD];
__device__ float g_q_part     [SPLITK * BB * DD];
__device__ float g_k_part     [SPLITK * BB * DD];
__device__ float g_v_part     [SPLITK * BB * DD];
__device__ float g_x          [BB * DD];
__device__ float g_vdraw_part [SPLITK * BB * DD];
__device__ float g_vdiff      [BB * DD];
__device__ float g_vdwg2      [BB];

// ---------------------------------------------------------------------------
// f32x2 packed helpers (FFMA2 — ptxas never emits this from C++)
// ---------------------------------------------------------------------------
__device__ __forceinline__ unsigned long long pack2(float x, float y) {
    unsigned long long r;
    asm("mov.b64 %0, {%1, %2};" : "=l"(r) : "f"(x), "f"(y));
    return r;
}
#define FMA2(acc, a, b) \
    asm("fma.rn.f32x2 %0, %1, %2, %3;" : "=l"(acc) : "l"(a), "l"(b), "l"(acc))

union U64F2 { unsigned long long u; float2 f; };

// ---------------------------------------------------------------------------
// Block reductions (small kernels only)
// ---------------------------------------------------------------------------
__device__ __forceinline__ float block_sum(float v, float* red) {
    #pragma unroll
    for (int o = 16; o > 0; o >>= 1) v += __shfl_xor_sync(0xffffffffu, v, o);
    int w = threadIdx.x >> 5, l = threadIdx.x & 31;
    if (l == 0) red[w] = v;
    __syncthreads();
    if (w == 0) {
        float x = (l < (int)(blockDim.x >> 5)) ? red[l] : 0.f;
        #pragma unroll
        for (int o = 4; o > 0; o >>= 1) x += __shfl_xor_sync(0xffffffffu, x, o);
        if (l == 0) red[0] = x;
    }
    __syncthreads();
    float r = red[0];
    __syncthreads();
    return r;
}

__device__ __forceinline__ float block_max(float v, float* red) {
    #pragma unroll
    for (int o = 16; o > 0; o >>= 1) v = fmaxf(v, __shfl_xor_sync(0xffffffffu, v, o));
    int w = threadIdx.x >> 5, l = threadIdx.x & 31;
    if (l == 0) red[w] = v;
    __syncthreads();
    if (w == 0) {
        float x = (l < (int)(blockDim.x >> 5)) ? red[l] : -1e30f;
        #pragma unroll
        for (int o = 4; o > 0; o >>= 1) x = fmaxf(x, __shfl_xor_sync(0xffffffffu, x, o));
        if (l == 0) red[0] = x;
    }
    __syncthreads();
    float r = red[0];
    __syncthreads();
    return r;
}

// ---------------------------------------------------------------------------
// GEMM core, occupancy-first: 256 threads, 32(M)x64(N) tile, micro 4m x 2n
// via 4 FFMA2 accumulators. KC=16 K-chunks, SPLITK=32 output slabs
// (deterministic, no atomics). Double-buffered smem, register prefetch,
// ONE barrier per chunk. A is stored duplicated (f32x2) for FFMA2; per-warp
// A reads broadcast (tm constant within a warp).
// ---------------------------------------------------------------------------
__device__ __forceinline__ void gemm_core(
    const float* __restrict__ Ap, int lda,
    const float* __restrict__ Bp, int ldb,
    float* __restrict__ Cp, int ldc,
    int N, int K, float alpha, int bkn, int kp, int n0)
{
    __shared__ unsigned long long As2[2][KC][34];
    __shared__ float Bs[2][KC][68];

    const int t  = threadIdx.x;
    const int tm = t >> 5;            // 0..7  -> rows 4*tm..4*tm+3
    const int tn = t & 31;            // 0..31 -> cols 2*tn, 2*tn+1

    // A-load mapping: 512 floats/chunk, float2 per thread
    const int am = t >> 3;            // 0..31
    const int ak = (t & 7) << 1;      // 0,2,..,14
    // B-load mapping (bkn==0): 1024 floats/chunk, float4 per thread
    const int bn  = t >> 2;           // 0..63
    const int bk  = (t & 3) << 2;     // 0,4,8,12
    // B-load mapping (bkn==1)
    const int bkc = t >> 4;           // 0..15
    const int bnq = (t & 15) << 2;    // 0..60

    unsigned long long acc[4];
    acc[0] = acc[1] = acc[2] = acc[3] = 0ull;

    const int nch = (K + KC - 1) / KC;
    float2 rA;
    float4 rB;

    auto loadA = [&](int k0, int kcur) {
        rA = make_float2(0.f, 0.f);
        const float* ap = Ap + (long)am * lda + k0 + ak;
        if (kcur == KC) {
            rA = *reinterpret_cast<const float2*>(ap);
        } else {
            if (ak     < kcur) rA.x = ap[0];
            if (ak + 1 < kcur) rA.y = ap[1];
        }
    };
    auto loadB = [&](int k0, int kcur) {
        rB = make_float4(0.f, 0.f, 0.f, 0.f);
        if (!bkn) {                       // B[N][K]
            int gn = n0 + bn;
            if (gn < N) {
                const float* bp = Bp + (long)gn * ldb + k0 + bk;
                if (kcur == KC) {
                    rB = *reinterpret_cast<const float4*>(bp);
                } else {
                    float* pv = &rB.x;
                    #pragma unroll
                    for (int j = 0; j < 4; j++)
                        if (bk + j < kcur) pv[j] = bp[j];
                }
            }
        } else {                          // B[K][N]
            int gn = n0 + bnq;
            if (bkc < kcur) {
                const float* bp = Bp + (long)(k0 + bkc) * ldb + gn;
                if (gn + 3 < N) {
                    rB = *reinterpret_cast<const float4*>(bp);
                } else {
                    float* pv = &rB.x;
                    #pragma unroll
                    for (int j = 0; j < 4; j++)
                        if (gn + j < N) pv[j] = bp[j];
                }
            }
        }
    };
    auto store = [&](int buf) {
        As2[buf][ak][am]     = pack2(rA.x, rA.x);
        As2[buf][ak + 1][am] = pack2(rA.y, rA.y);
        if (!bkn) {
            Bs[buf][bk + 0][bn] = rB.x;
            Bs[buf][bk + 1][bn] = rB.y;
            Bs[buf][bk + 2][bn] = rB.z;
            Bs[buf][bk + 3][bn] = rB.w;
        } else {
            *reinterpret_cast<float4*>(&Bs[buf][bkc][bnq]) = rB;
        }
    };

    int c = kp;
    {
        int k0 = c * KC;
        int kcur = K - k0; if (kcur > KC) kcur = KC;
        loadA(k0, kcur);
        loadB(k0, kcur);
    }
    store(0);
    __syncthreads();

    int p = 0;
    while (true) {
        int nxt = c + SPLITK;
        bool has = nxt < nch;
        if (has) {
            int k0 = nxt * KC;
            int kcur = K - k0; if (kcur > KC) kcur = KC;
            loadA(k0, kcur);
            loadB(k0, kcur);
        }
        #pragma unroll
        for (int kc = 0; kc < KC; kc++) {
            ulonglong2 a01 = *reinterpret_cast<const ulonglong2*>(&As2[p][kc][tm << 2]);
            ulonglong2 a23 = *reinterpret_cast<const ulonglong2*>(&As2[p][kc][(tm << 2) + 2]);
            unsigned long long b = *reinterpret_cast<const unsigned long long*>(&Bs[p][kc][tn << 1]);
            FMA2(acc[0], a01.x, b);
            FMA2(acc[1], a01.y, b);
            FMA2(acc[2], a23.x, b);
            FMA2(acc[3], a23.y, b);
        }
        if (!has) break;
        store(1 - p);
        __syncthreads();
        p ^= 1;
        c = nxt;
    }

    // epilogue: unpack + store partial slab
    #pragma unroll
    for (int i = 0; i < 4; i++) {
        U64F2 u; u.u = acc[i];
        long roff = (long)((tm << 2) + i) * ldc;
        int gn = n0 + (tn << 1);
        if (gn < N)     Cp[roff + gn]     = u.f.x * alpha;
        if (gn + 1 < N) Cp[roff + gn + 1] = u.f.y * alpha;
    }
}

// ---------------------------------------------------------------------------
// Generic wrapper: grid.x = ntilesN*SPLITK, grid.y = M/32, grid.z = batch
// ---------------------------------------------------------------------------
__global__ __launch_bounds__(NTHREADS) void gemm_kernel(
    const float* __restrict__ A, int lda, long sAz,
    const float* __restrict__ B, int ldb, long sBz,
    float* __restrict__ C, int ldc, long sCz, long sCkp,
    int N, int K, float alpha, int bkn)
{
    const int nt = blockIdx.x / SPLITK;
    const int kp = blockIdx.x % SPLITK;
    const int n0 = nt * TN;
    const int m0 = blockIdx.y * 32;
    const float* Ap = A + (long)blockIdx.z * sAz + (long)m0 * lda;
    const float* Bp = B + (long)blockIdx.z * sBz;
    float*       Cp = C + (long)kp * sCkp + (long)blockIdx.z * sCz + (long)m0 * ldc;
    gemm_core(Ap, lda, Bp, ldb, Cp, ldc, N, K, alpha, bkn, kp, n0);
}

// ---------------------------------------------------------------------------
// Merged q/k/v wrapper: z=0: fc@Wq, z=1: vagg@Wk, z=2: vagg@Wv
// ---------------------------------------------------------------------------
__global__ __launch_bounds__(NTHREADS) void qkv_kernel(
    const float* __restrict__ fc, const float* __restrict__ vagg,
    const float* __restrict__ Wq, const float* __restrict__ Wk,
    const float* __restrict__ Wv,
    float* __restrict__ qp, float* __restrict__ kp_, float* __restrict__ vp)
{
    const int z  = blockIdx.z;
    const int nt = blockIdx.x / SPLITK;
    const int kp = blockIdx.x % SPLITK;
    const int n0 = nt * TN;
    const float* A = (z == 0) ? fc : vagg;
    const float* B = (z == 0) ? Wq : ((z == 1) ? Wk : Wv);
    float*       C = (z == 0) ? qp : ((z == 1) ? kp_ : vp);
    float*       Cp = C + (long)kp * (long)BB * DD;
    gemm_core(A, DD, B, DD, Cp, DD, DD, DD, 1.f, 0, kp, n0);
}

// ---------------------------------------------------------------------------
// Sum nslabs contiguous slabs of `elems` floats
// ---------------------------------------------------------------------------
__global__ __launch_bounds__(256) void reduce_slabs_kernel(
    const float* __restrict__ src, float* __restrict__ dst, int elems, int nslabs)
{
    int i = blockIdx.x * 256 + threadIdx.x;
    if (i < elems) {
        float s = 0.f;
        for (int k = 0; k < nslabs; k++) s += src[(long)k * elems + i];
        dst[i] = s;
    }
}

// ---------------------------------------------------------------------------
// Softmax over P for each of the 96 rows; input = SPLITK slabs of scores
// ---------------------------------------------------------------------------
__global__ __launch_bounds__(256) void softmax_kernel(
    const float* __restrict__ sp, float* __restrict__ w)
{
    const int row = blockIdx.x;
    const int t = threadIdx.x;
    __shared__ float buf[PP];
    __shared__ float red[8];
    const long base = (long)row * PP;
    const long slab = (long)RR * BB * PP;

    float mx = -1e30f;
    for (int p = t; p < PP; p += 256) {
        float s = 0.f;
        for (int k = 0; k < SPLITK; k++) s += sp[(long)k * slab + base + p];
        buf[p] = s;
        mx = fmaxf(mx, s);
    }
    float m = block_max(mx, red);

    float sum = 0.f;
    for (int p = t; p < PP; p += 256) {
        float e = __expf(buf[p] - m);
        buf[p] = e;
        sum += e;
    }
    float S = block_sum(sum, red);
    float inv = 1.f / S;
    for (int p = t; p < PP; p += 256) w[base + p] = buf[p] * inv;
}

// ---------------------------------------------------------------------------
// sim = <q+bq, k+bk>*scale per batch; x = vhat - sigmoid(sim)*(v+bv)
// ---------------------------------------------------------------------------
__global__ __launch_bounds__(256) void simx_kernel(
    const float* __restrict__ qp, const float* __restrict__ kp,
    const float* __restrict__ vp,
    const float* __restrict__ bq, const float* __restrict__ bk,
    const float* __restrict__ bv,
    const float* __restrict__ fc, float* __restrict__ x)
{
    const int b = blockIdx.x;
    const int t = threadIdx.x;
    __shared__ float red[8];
    const long slab = (long)BB * DD;

    float partial = 0.f;
    for (int d = t; d < DD; d += 256) {
        long idx = (long)b * DD + d;
        float qv = bq[d], kv = bk[d];
        for (int s = 0; s < SPLITK; s++) {
            qv += qp[(long)s * slab + idx];
            kv += kp[(long)s * slab + idx];
        }
        partial = fmaf(qv, kv, partial);
    }
    float sim = block_sum(partial, red) * SCALE;
    float sg = 1.f / (1.f + __expf(-sim));

    for (int d = t; d < DD; d += 256) {
        long idx = (long)b * DD + d;
        float vv = bv[d];
        for (int s = 0; s < SPLITK; s++) vv += vp[(long)s * slab + idx];
        x[idx] = fc[idx] - sg * vv;
    }
}

// ---------------------------------------------------------------------------
// v_diff = relu(vdraw + bc); vdwg2[b] = <v_diff[b], Wg2>
// ---------------------------------------------------------------------------
__global__ __launch_bounds__(256) void relu_wg2_kernel(
    const float* __restrict__ vdp, const float* __restrict__ bc,
    const float* __restrict__ Wg, float* __restrict__ vdiff,
    float* __restrict__ vdwg2)
{
    const int b = blockIdx.x;
    const int t = threadIdx.x;
    __shared__ float red[8];
    const long slab = (long)BB * DD;
    const float* Wg2 = Wg + DD;

    float partial = 0.f;
    for (int d = t; d < DD; d += 256) {
        long idx = (long)b * DD + d;
        float r = bc[d];
        for (int s = 0; s < SPLITK; s++) r += vdp[(long)s * slab + idx];
        r = fmaxf(r, 0.f);
        vdiff[idx] = r;
        partial = fmaf(r, Wg2[d], partial);
    }
    float tot = block_sum(partial, red);
    if (t == 0) vdwg2[b] = tot;
}

// ---------------------------------------------------------------------------
// Final fused pass, warp-per-row (no barriers in the hot path).
// ---------------------------------------------------------------------------
__global__ __launch_bounds__(256) void final_kernel(
    const float* __restrict__ att, const float* __restrict__ Wg,
    const float* __restrict__ vdiff, const float* __restrict__ vdwg2,
    const float* __restrict__ bg, const float* __restrict__ rs,
    float* __restrict__ out)
{
    const int warp = threadIdx.x >> 5;
    const int lane = threadIdx.x & 31;
    const int row  = blockIdx.x * 8 + warp;       // 0 .. B*NI-1
    const int b    = row >> 10;                   // row / NI_
    const long base = (long)row * DD;

    float4 a[8];
    float partial = 0.f;
    #pragma unroll
    for (int i = 0; i < 8; i++) {
        int d = (i * 32 + lane) * 4;
        a[i] = *reinterpret_cast<const float4*>(att + base + d);
        float4 wv = *reinterpret_cast<const float4*>(Wg + d);
        partial += a[i].x * wv.x + a[i].y * wv.y + a[i].z * wv.z + a[i].w * wv.w;
    }
    #pragma unroll
    for (int o = 16; o > 0; o >>= 1)
        partial += __shfl_xor_sync(0xffffffffu, partial, o);

    float g = 1.f / (1.f + __expf(-(partial + vdwg2[b] + bg[0])));
    float r = rs[0] * g;

    #pragma unroll
    for (int i = 0; i < 8; i++) {
        int d = (i * 32 + lane) * 4;
        float4 vd = *reinterpret_cast<const float4*>(vdiff + (long)b * DD + d);
        float4 o4;
        o4.x = fmaf(r, vd.x, a[i].x);
        o4.y = fmaf(r, vd.y, a[i].y);
        o4.z = fmaf(r, vd.z, a[i].z);
        o4.w = fmaf(r, vd.w, a[i].w);
        *reinterpret_cast<float4*>(out + base + d) = o4;
    }
}

// ---------------------------------------------------------------------------
// Launch
// ---------------------------------------------------------------------------
extern "C" void kernel_launch(void* const* d_in, const int* in_sizes, int n_in,
                              void* d_out, int out_size)
{
    const float* att  = (const float*)d_in[0];
    const float* fc   = (const float*)d_in[1];
    const float* pool = (const float*)d_in[2];
    const float* Wagg = (const float*)d_in[3];
    const float* Wq   = (const float*)d_in[4];
    const float* bq   = (const float*)d_in[5];
    const float* Wk   = (const float*)d_in[6];
    const float* bk   = (const float*)d_in[7];
    const float* Wv   = (const float*)d_in[8];
    const float* bv   = (const float*)d_in[9];
    const float* Wc   = (const float*)d_in[10];
    const float* bc   = (const float*)d_in[11];
    const float* Wg   = (const float*)d_in[12];
    const float* bg   = (const float*)d_in[13];
    const float* rs   = (const float*)d_in[14];
    float* out = (float*)d_out;

    float *qall_part, *qall, *scores_part, *weights, *vagg_part, *vagg;
    float *q_part, *k_part, *v_part, *x, *vdraw_part, *vdiff, *vdwg2;
    cudaGetSymbolAddress((void**)&qall_part,   g_qall_part);
    cudaGetSymbolAddress((void**)&qall,        g_qall);
    cudaGetSymbolAddress((void**)&scores_part, g_scores_part);
    cudaGetSymbolAddress((void**)&weights,     g_weights);
    cudaGetSymbolAddress((void**)&vagg_part,   g_vagg_part);
    cudaGetSymbolAddress((void**)&vagg,        g_vagg);
    cudaGetSymbolAddress((void**)&q_part,      g_q_part);
    cudaGetSymbolAddress((void**)&k_part,      g_k_part);
    cudaGetSymbolAddress((void**)&v_part,      g_v_part);
    cudaGetSymbolAddress((void**)&x,           g_x);
    cudaGetSymbolAddress((void**)&vdraw_part,  g_vdraw_part);
    cudaGetSymbolAddress((void**)&vdiff,       g_vdiff);
    cudaGetSymbolAddress((void**)&vdwg2,       g_vdwg2);

    const long BD   = (long)BB * DD;       // 32768
    const long RBD  = (long)RR * BD;       // 98304
    const long RBP  = (long)RR * BB * PP;  // 96000
    const int  NT16 = 16 * SPLITK;         // ntilesN(16) * SPLITK

    // 1) q_all[r,b,o] = vhat @ W_agg[r]^T  -> SPLITK slabs
    gemm_kernel<<<dim3(NT16, 1, RR), NTHREADS>>>(
        fc, DD, 0L, Wagg, DD, (long)DD * DD,
        qall_part, DD, BD, RBD, DD, DD, 1.f, 0);
    reduce_slabs_kernel<<<(int)((RBD + 255) / 256), 256>>>(
        qall_part, qall, (int)RBD, SPLITK);

    // 2) scores[rb,p] = q_all @ pool^T * scale
    gemm_kernel<<<dim3(NT16, 3, 1), NTHREADS>>>(
        qall, DD, 0L, pool, DD, 0L,
        scores_part, PP, 0L, RBP, PP, DD, SCALE, 0);

    // 3) softmax over P per row (sums SPLITK slabs internally)
    softmax_kernel<<<96, 256>>>(scores_part, weights);

    // 4) vagg[b,d] = (1/R) * sum_r weights[r] @ pool
    gemm_kernel<<<dim3(NT16, 1, RR), NTHREADS>>>(
        weights, PP, (long)BB * PP, pool, DD, 0L,
        vagg_part, DD, BD, RR * BD, DD, PP, 1.f / 3.f, 1);
    reduce_slabs_kernel<<<(int)((BD + 255) / 256), 256>>>(
        vagg_part, vagg, (int)BD, SPLITK * RR);

    // 5) q, k, v in ONE launch (z planes), left as SPLITK slabs
    qkv_kernel<<<dim3(NT16, 1, 3), NTHREADS>>>(
        fc, vagg, Wq, Wk, Wv, q_part, k_part, v_part);

    // 6) sim + v_common + x = vhat - v_common
    simx_kernel<<<BB, 256>>>(q_part, k_part, v_part, bq, bk, bv, fc, x);

    // 7) vdraw = x @ Wc^T
    gemm_kernel<<<dim3(NT16, 1, 1), NTHREADS>>>(
        x, DD, 0L, Wc, DD, 0L, vdraw_part, DD, 0L, BD, DD, DD, 1.f, 0);

    // 8) v_diff = relu(vdraw + bc); vdwg2 = v_diff @ Wg2
    relu_wg2_kernel<<<BB, 256>>>(vdraw_part, bc, Wg, vdiff, vdwg2);

    // 9) fused gate + residual over att_feats (dominant, DRAM-bound)
    final_kernel<<<4096, 256>>>(att, Wg, vdiff, vdwg2, bg, rs, out);
}